// round 14
// baseline (speedup 1.0000x reference)
#include <cuda_runtime.h>
#include <cuda_bf16.h>
#include <cstdint>

// DLRM dot-interaction, BF16 tensor cores, 3-term split, persistent CTAs.
// Pipeline per CTA (64 thr, 2 warps, split-k 64 dims each):
//   prologue: LDG sample s0 -> regs, split -> bf16 hi/lo planes in smem
//   loop:     [1] issue LDG s+stride (lands during compute)
//             [2] compute s from planes (pure LDS.32 + HMMA)
//             [3] sync; exchange-STS + convert s+stride -> planes
//             [4] sync; epilogue (reduce + STG triu); sync
// Planes: 32 rows x 136 bf16 (272B stride = 16 mod 128 -> conflict-free frags).
// Split: x = hi(trunc bf16, exact top16) + lo(rn-bf16 of fp32 residual);
// 3 mmas/position (ah*bh + ah*bl + al*bh), dropped al*bl ~ 2^-16.

constexpr int Bt    = 16384;
constexpr int NE    = 26;
constexpr int D     = 128;
constexpr int N     = 27;
constexpr int NPAIR = N * (N - 1) / 2;     // 351
constexpr int STRH  = 136;                 // shorts per plane row
constexpr int NTHR  = 64;
constexpr int NTILE = 6;
constexpr int GRID  = 888;                 // ~6+ CTAs/SM x 148 SMs
constexpr int NF4   = 864;                 // float4 per sample (27 rows x 32)

__device__ __forceinline__ void mma_bf16(float* c,
    uint32_t a0, uint32_t a1, uint32_t a2, uint32_t a3,
    uint32_t b0, uint32_t b1)
{
    asm volatile(
        "mma.sync.aligned.m16n8k16.row.col.f32.bf16.bf16.f32 "
        "{%0,%1,%2,%3}, {%4,%5,%6,%7}, {%8,%9}, {%0,%1,%2,%3};"
        : "+f"(c[0]), "+f"(c[1]), "+f"(c[2]), "+f"(c[3])
        : "r"(a0), "r"(a1), "r"(a2), "r"(a3), "r"(b0), "r"(b1));
}

__global__ void __launch_bounds__(NTHR)
dot_interaction_kernel(const float* __restrict__ dense,
                       const float* __restrict__ embs,
                       float* __restrict__ out)
{
    __shared__ uint16_t Shi[32 * STRH];    // 8704 B
    __shared__ uint16_t Slo[32 * STRH];    // 8704 B
    __shared__ float    Sx[768];           // 3072 B exchange

    const int tid  = threadIdx.x;
    const int kw   = tid >> 5;
    const int lane = tid & 31;
    const int g    = lane >> 2;
    const int t4   = lane & 3;
    const int stride = gridDim.x;

    // Zero pad rows 27..31 of both planes (cols 0..135) once.
    for (int i = tid; i < 5 * (STRH / 2); i += NTHR) {   // 340 uint32 per plane
        reinterpret_cast<uint32_t*>(&Shi[27 * STRH])[i] = 0u;
        reinterpret_cast<uint32_t*>(&Slo[27 * STRH])[i] = 0u;
    }

    // Staged-load + convert helpers -------------------------------------------
    float4 st[14];
    auto ldg_stage = [&](int s) {
        const float4* d4 = reinterpret_cast<const float4*>(dense + (size_t)s * D);
        const float4* e4 = reinterpret_cast<const float4*>(embs + (size_t)s * NE * D);
        #pragma unroll
        for (int i = 0; i < 14; i++) {
            const int idx = tid + i * NTHR;
            if (i < 13 || idx < NF4)
                st[i] = (idx < 32) ? d4[idx] : e4[idx - 32];
        }
    };
    auto convert_store = [&]() {
        #pragma unroll
        for (int i = 0; i < 14; i++) {
            const int idx = tid + i * NTHR;
            if (i == 13 && idx >= NF4) break;
            const int row = idx >> 5, c0 = (idx & 31) * 4;   // 4 cols, c0 multiple of 4
            const float4 v = st[i];
            const uint32_t bx = __float_as_uint(v.x), by = __float_as_uint(v.y);
            const uint32_t bz = __float_as_uint(v.z), bw = __float_as_uint(v.w);
            uint32_t* hp = reinterpret_cast<uint32_t*>(&Shi[row * STRH + c0]);
            uint32_t* lp = reinterpret_cast<uint32_t*>(&Slo[row * STRH + c0]);
            hp[0] = __byte_perm(bx, by, 0x7632);
            hp[1] = __byte_perm(bz, bw, 0x7632);
            __nv_bfloat162 l0 = __floats2bfloat162_rn(
                v.x - __uint_as_float(bx & 0xFFFF0000u),
                v.y - __uint_as_float(by & 0xFFFF0000u));
            __nv_bfloat162 l1 = __floats2bfloat162_rn(
                v.z - __uint_as_float(bz & 0xFFFF0000u),
                v.w - __uint_as_float(bw & 0xFFFF0000u));
            lp[0] = *reinterpret_cast<uint32_t*>(&l0);
            lp[1] = *reinterpret_cast<uint32_t*>(&l1);
        }
    };

    // Prologue: stage + convert first sample
    int s = blockIdx.x;
    ldg_stage(s);
    convert_store();
    __syncthreads();

    constexpr int MT[NTILE] = {0, 0, 0, 0, 1, 1};
    constexpr int NT[NTILE] = {0, 1, 2, 3, 2, 3};

    for (; s < Bt; s += stride) {
        const int snext = s + stride;
        if (snext < Bt) ldg_stage(snext);          // lands during compute

        // ---- Compute: pure LDS.32 + HMMA from planes ----
        float acc[NTILE][4];
        #pragma unroll
        for (int e = 0; e < NTILE; e++)
            #pragma unroll
            for (int c = 0; c < 4; c++) acc[e][c] = 0.f;

        const int kbase = kw * 64;
        #pragma unroll
        for (int kt = 0; kt < 4; kt++) {
            const int kc = kbase + kt * 16 + 2 * t4;
            uint32_t bh[4][2], bl[4][2];
            #pragma unroll
            for (int nt = 0; nt < 4; nt++) {
                const int n = nt * 8 + g;
                bh[nt][0] = *reinterpret_cast<const uint32_t*>(&Shi[n * STRH + kc    ]);
                bh[nt][1] = *reinterpret_cast<const uint32_t*>(&Shi[n * STRH + kc + 8]);
                bl[nt][0] = *reinterpret_cast<const uint32_t*>(&Slo[n * STRH + kc    ]);
                bl[nt][1] = *reinterpret_cast<const uint32_t*>(&Slo[n * STRH + kc + 8]);
            }
            #pragma unroll
            for (int e = 0; e < NTILE; e++) {
                float* c = acc[e];
                const int m2 = 2 * MT[e], n = NT[e];
                mma_bf16(c, bl[m2][0], bl[m2+1][0], bl[m2][1], bl[m2+1][1],
                            bh[n][0],  bh[n][1]);
                mma_bf16(c, bh[m2][0], bh[m2+1][0], bh[m2][1], bh[m2+1][1],
                            bl[n][0],  bl[n][1]);
                mma_bf16(c, bh[m2][0], bh[m2+1][0], bh[m2][1], bh[m2+1][1],
                            bh[n][0],  bh[n][1]);
            }
        }

        __syncthreads();                           // plane reads done

        // ---- Exchange (separate buffer) + convert next sample into planes ----
        if (kw == 1) {
            #pragma unroll
            for (int e = 0; e < 3; e++)
                #pragma unroll
                for (int c = 0; c < 4; c++)
                    Sx[(e * 4 + c) * 32 + lane] = acc[e][c];
        } else {
            #pragma unroll
            for (int e = 3; e < 6; e++)
                #pragma unroll
                for (int c = 0; c < 4; c++)
                    Sx[384 + ((e - 3) * 4 + c) * 32 + lane] = acc[e][c];
        }
        if (snext < Bt) convert_store();           // staging regs -> planes
        __syncthreads();                           // exchange + planes visible

        // ---- Epilogue: each warp reduces+stores its 3 tiles ----
        {
            float* orow = out + (size_t)s * NPAIR;
            const int e0  = (kw == 0) ? 0 : 3;
            const int off = (kw == 0) ? 0 : 384;
            #pragma unroll
            for (int q = 0; q < 3; q++) {
                const int e = e0 + q;
                #pragma unroll
                for (int c = 0; c < 4; c++) {
                    const float v = acc[e][c] + Sx[off + (q * 4 + c) * 32 + lane];
                    const int i = MT[e] * 16 + g + ((c & 2) ? 8 : 0);
                    const int j = NT[e] * 8 + 2 * t4 + (c & 1);
                    if (i < j && j < N)
                        orow[i * (2 * N - 1 - i) / 2 + (j - i - 1)] = v;
                }
            }
        }
        __syncthreads();                           // Sx reads done before reuse
    }
}

extern "C" void kernel_launch(void* const* d_in, const int* in_sizes, int n_in,
                              void* d_out, int out_size)
{
    const float* dense = (const float*)d_in[0];
    const float* embs  = (const float*)d_in[1];
    float* out = (float*)d_out;
    dot_interaction_kernel<<<GRID, NTHR>>>(dense, embs, out);
}

// round 15
// speedup vs baseline: 1.1736x; 1.1736x over previous
#include <cuda_runtime.h>
#include <cuda_bf16.h>
#include <cstdint>

// DLRM dot-interaction via BF16 tensor cores, 3-term split.
// One sample per 128-thread CTA, FOUR warps split-k (32 dims each) sharing one
// fp32 tile (17.4KB) -> 8.7KB smem per 2 warps halves to 4.35KB/warp, lifting
// the SM warp cap from 26 to 52. Work per sample unchanged from R10; reduction
// is 4-way via the dead tile smem, tiles divided 2/2/1/1 across warps.

constexpr int Bt    = 16384;
constexpr int NE    = 26;
constexpr int D     = 128;
constexpr int N     = 27;
constexpr int NPAIR = N * (N - 1) / 2;     // 351
constexpr int STRF  = 136;                 // floats per smem row
constexpr int STR4  = 34;                  // float4 per smem row
constexpr int NTHR  = 128;
constexpr int NWARP = 4;
constexpr int NTILE = 6;
constexpr int NF4   = 864;                 // float4 per sample (27 rows x 32)

__device__ __forceinline__ void mma_bf16(float* c,
    uint32_t a0, uint32_t a1, uint32_t a2, uint32_t a3,
    uint32_t b0, uint32_t b1)
{
    asm volatile(
        "mma.sync.aligned.m16n8k16.row.col.f32.bf16.bf16.f32 "
        "{%0,%1,%2,%3}, {%4,%5,%6,%7}, {%8,%9}, {%0,%1,%2,%3};"
        : "+f"(c[0]), "+f"(c[1]), "+f"(c[2]), "+f"(c[3])
        : "r"(a0), "r"(a1), "r"(a2), "r"(a3), "r"(b0), "r"(b1));
}

// Split a float2 into packed bf16 (hi, lo). hi = trunc-bf16 (exact top 16 bits,
// one PRMT); lo = rn-bf16 of the exact fp32 residual.
__device__ __forceinline__ void split2(float2 v, uint32_t& hi, uint32_t& lo)
{
    const uint32_t bx = __float_as_uint(v.x), by = __float_as_uint(v.y);
    hi = __byte_perm(bx, by, 0x7632);
    const float lx = v.x - __uint_as_float(bx & 0xFFFF0000u);
    const float ly = v.y - __uint_as_float(by & 0xFFFF0000u);
    __nv_bfloat162 l2 = __floats2bfloat162_rn(lx, ly);
    lo = *reinterpret_cast<uint32_t*>(&l2);
}

__global__ void __launch_bounds__(NTHR)
dot_interaction_kernel(const float* __restrict__ dense,
                       const float* __restrict__ embs,
                       float* __restrict__ out)
{
    __shared__ float S[32 * STRF];                   // 17408 B

    const int tid  = threadIdx.x;
    const int kq   = tid >> 5;                       // k-quarter: 0..3
    const int lane = tid & 31;
    const int g    = lane >> 2;
    const int t4   = lane & 3;
    const int sample = blockIdx.x;

    // ---- Load phase: 128 threads stage T (32x128 fp32, rows 27..31 zero) ----
    float4* S4 = reinterpret_cast<float4*>(S);
    const float4* d4 = reinterpret_cast<const float4*>(dense + (size_t)sample * D);
    const float4* e4 = reinterpret_cast<const float4*>(embs + (size_t)sample * NE * D);

    #pragma unroll
    for (int i = 0; i < 7; i++) {                    // 864 f4 over 128 threads
        const int idx = tid + i * NTHR;
        if (idx < NF4) {
            const int row = idx >> 5, col = idx & 31;
            S4[row * STR4 + col] = (idx < 32) ? d4[idx] : e4[idx - 32];
        }
    }
    #pragma unroll
    for (int i = tid; i < 5 * STR4; i += NTHR)       // rows 27..31 = zero
        S4[27 * STR4 + i] = make_float4(0.f, 0.f, 0.f, 0.f);
    __syncthreads();

    // Upper-triangle tile list: e -> (mt, nt)
    constexpr int MT[NTILE] = {0, 0, 0, 0, 1, 1};
    constexpr int NT[NTILE] = {0, 1, 2, 3, 2, 3};

    float acc[NTILE][4];
    #pragma unroll
    for (int e = 0; e < NTILE; e++)
        #pragma unroll
        for (int c = 0; c < 4; c++) acc[e][c] = 0.f;

    // ---- Compute: this warp covers dims [kq*32, kq*32+32) = 2 ktiles ----
    #pragma unroll
    for (int kt = 0; kt < 2; kt++) {
        const int kc = kq * 32 + kt * 16 + 2 * t4;

        uint32_t bh[4][2], bl[4][2];                 // B frags; A aliases them
        #pragma unroll
        for (int nt = 0; nt < 4; nt++) {
            const int n = nt * 8 + g;
            split2(*reinterpret_cast<const float2*>(&S[n * STRF + kc    ]), bh[nt][0], bl[nt][0]);
            split2(*reinterpret_cast<const float2*>(&S[n * STRF + kc + 8]), bh[nt][1], bl[nt][1]);
        }
        #pragma unroll
        for (int e = 0; e < NTILE; e++) {
            float* c = acc[e];
            const int m2 = 2 * MT[e], n = NT[e];
            mma_bf16(c, bl[m2][0], bl[m2+1][0], bl[m2][1], bl[m2+1][1],
                        bh[n][0],  bh[n][1]);
            mma_bf16(c, bh[m2][0], bh[m2+1][0], bh[m2][1], bh[m2+1][1],
                        bl[n][0],  bl[n][1]);
            mma_bf16(c, bh[m2][0], bh[m2+1][0], bh[m2][1], bh[m2+1][1],
                        bh[n][0],  bh[n][1]);
        }
    }

    // ---- 4-way reduction via dead tile smem ----
    __syncthreads();                                 // all tile reads done
    // Partial layout: P(w,e,c,lane) = ((w*6+e)*4+c)*32 + lane  (3072 floats)
    #pragma unroll
    for (int e = 0; e < NTILE; e++)
        #pragma unroll
        for (int c = 0; c < 4; c++)
            S[((kq * NTILE + e) * 4 + c) * 32 + lane] = acc[e][c];
    __syncthreads();

    // ---- Epilogue: tiles divided across warps (w0:{0,1} w1:{2,3} w2:{4} w3:{5}) ----
    const int ebeg = (kq < 2) ? kq * 2 : kq + 2;     // 0,2,4,5
    const int eend = (kq < 2) ? ebeg + 2 : ebeg + 1; // 2,4,5,6
    float* orow = out + (size_t)sample * NPAIR;
    for (int e = ebeg; e < eend; e++) {
        #pragma unroll
        for (int c = 0; c < 4; c++) {
            float v = S[((0 * NTILE + e) * 4 + c) * 32 + lane]
                    + S[((1 * NTILE + e) * 4 + c) * 32 + lane]
                    + S[((2 * NTILE + e) * 4 + c) * 32 + lane]
                    + S[((3 * NTILE + e) * 4 + c) * 32 + lane];
            const int i = MT[e] * 16 + g + ((c & 2) ? 8 : 0);
            const int j = NT[e] * 8 + 2 * t4 + (c & 1);
            if (i < j && j < N)
                orow[i * (2 * N - 1 - i) / 2 + (j - i - 1)] = v;
        }
    }
}

extern "C" void kernel_launch(void* const* d_in, const int* in_sizes, int n_in,
                              void* d_out, int out_size)
{
    const float* dense = (const float*)d_in[0];
    const float* embs  = (const float*)d_in[1];
    float* out = (float*)d_out;
    dot_interaction_kernel<<<Bt, NTHR>>>(dense, embs, out);
}